// round 15
// baseline (speedup 1.0000x reference)
#include <cuda_runtime.h>
#include <cuda_bf16.h>
#include <math.h>
#include <stdint.h>

#define NN 50000
#define EE 800000
#define NB 296          // resident blocks for fused CSR kernel (148 SMs x 2)

// packed-weight offsets in uint32 (bf162-pair) units, layout [K/2][NC]
#define OFF_F2H   0
#define OFF_C2HE  8192
#define OFF_C2HD  12288
#define OFF_ML    16384
#define OFF_Z2H   24576
#define OFF_OUT   26624
#define W_TOTAL32 43008

// ---------------- scratch (static __device__, no runtime allocation) ----------------
__device__ float g_dis[NN];
__device__ int   g_deg[NN];
__device__ int   g_off[NN + 1];
__device__ int   g_cur[NN];
__device__ int   g_rows[EE];
__device__ int   g_cols[EE];
__device__ int   g_srows[EE];
__device__ float g_senorm[EE];
__device__ float g_P  [NN * 64];
__device__ float g_O  [NN * 128];
__device__ float g_bml[64];
__device__ __nv_bfloat16 g_AfcH[NN * 192], g_AfcL[NN * 192];
__device__ __nv_bfloat16 g_H2H [NN * 256], g_H2L [NN * 256];
__device__ __nv_bfloat16 g_HDH [NN * 256], g_HDL [NN * 256];
__device__ __nv_bfloat16 g_AzH [NN * 32],  g_AzL [NN * 32];
__device__ uint32_t g_WH32[W_TOTAL32], g_WL32[W_TOTAL32];
__device__ unsigned g_cnt;
__device__ int   g_part[512];

// ---------------- helpers ----------------
__device__ __forceinline__ uint32_t smem_u32(const void* p) {
    uint32_t a;
    asm("{ .reg .u64 t; cvta.to.shared.u64 t, %1; cvt.u32.u64 %0, t; }" : "=r"(a) : "l"(p));
    return a;
}
__device__ __forceinline__ void cp16(uint32_t dst, const void* src, uint32_t sz) {
    asm volatile("cp.async.ca.shared.global [%0], [%1], 16, %2;"
                 :: "r"(dst), "l"(__cvta_generic_to_global(src)), "r"(sz) : "memory");
}
#define CP_COMMIT() asm volatile("cp.async.commit_group;" ::: "memory")
#define CP_WAIT(N)  asm volatile("cp.async.wait_group %0;" :: "n"(N) : "memory")

// software grid barrier (all blocks co-resident)
__device__ __forceinline__ void gbar(unsigned step) {
    __syncthreads();
    if (threadIdx.x == 0) {
        __threadfence();
        atomicAdd(&g_cnt, 1u);
        unsigned target = step * gridDim.x;
        while (*(volatile unsigned*)&g_cnt < target) { }
        __threadfence();
    }
    __syncthreads();
}

// ---------------- fused CSR build ----------------
__global__ __launch_bounds__(256) void k_csr(const void* p, int e, int n) {
    int tid = threadIdx.x, bid = blockIdx.x;
    int gsz = gridDim.x * 256;
    int gi  = bid * 256 + tid;
    __shared__ int sh[256];

    const long long* q64 = (const long long*)p;
    long long probe = 0;
    if (gi < e) probe = q64[gi];
    int okl = (probe >= 0 && probe < (long long)n) ? 1 : 0;
    int is64 = __syncthreads_and(okl);

    for (int i = gi; i < e; i += gsz) {
        int r, c;
        if (is64) { r = (int)q64[i]; c = (int)q64[e + i]; }
        else { const int* q32 = (const int*)p; r = q32[i]; c = q32[e + i]; }
        g_rows[i] = r;
        g_cols[i] = c;
        atomicAdd(&g_deg[c], 1);
    }
    gbar(1);

    int chunk = (n + gridDim.x - 1) / gridDim.x;
    int s  = bid * chunk;
    int en = s + chunk; if (en > n) en = n;
    {
        int sum = 0;
        for (int i = s + tid; i < en; i += 256) sum += g_deg[i];
        sh[tid] = sum;
        __syncthreads();
        for (int o = 128; o > 0; o >>= 1) {
            if (tid < o) sh[tid] += sh[tid + o];
            __syncthreads();
        }
        if (tid == 0) g_part[bid] = sh[0];
    }
    gbar(2);

    int base;
    {
        int b = 0;
        for (int i = tid; i < bid; i += 256) b += g_part[i];
        __syncthreads();
        sh[tid] = b;
        __syncthreads();
        for (int o = 128; o > 0; o >>= 1) {
            if (tid < o) sh[tid] += sh[tid + o];
            __syncthreads();
        }
        base = sh[0];
        __syncthreads();
    }

    {
        int i = s + tid;
        int live = (tid < en - s);
        int d = live ? g_deg[i] : 0;
        sh[tid] = d;
        __syncthreads();
        for (int o = 1; o < 256; o <<= 1) {
            int v = (tid >= o) ? sh[tid - o] : 0;
            __syncthreads();
            sh[tid] += v;
            __syncthreads();
        }
        int excl = base + sh[tid] - d;
        if (live) {
            g_off[i] = excl;
            g_cur[i] = excl;
            g_dis[i] = rsqrtf((float)d + 1.0f);
        }
        if (bid == gridDim.x - 1 && tid == 0) g_off[n] = e;
    }
    gbar(3);

    for (int i = gi; i < e; i += gsz) {
        int r = g_rows[i], c = g_cols[i];
        int pos = atomicAdd(&g_cur[c], 1);
        g_srows[pos]  = r;
        g_senorm[pos] = g_dis[r] * g_dis[c];
    }
}

// ---------------- weight pre-pack: fp32 -> bf162-pair hi/lo planes, [K/2][NC] ----------------
__global__ void k_packw(const float* __restrict__ Wf2h, const float* __restrict__ Wc2he,
                        const float* __restrict__ Wc2hd, const float* __restrict__ Wm,
                        const float* __restrict__ Wlv, const float* __restrict__ Wz2h,
                        const float* __restrict__ Wout,
                        const float* __restrict__ bm, const float* __restrict__ bl) {
    int idx = blockIdx.x * 256 + threadIdx.x;
    if (idx < 64) g_bml[idx] = (idx < 32) ? bm[idx] : bl[idx - 32];
    if (idx >= W_TOTAL32) return;
    float v0, v1;
    if (idx < OFF_C2HE) {
        int j = idx, kp = j / 128, n = j % 128;
        v0 = Wf2h[(2 * kp) * 128 + n]; v1 = Wf2h[(2 * kp + 1) * 128 + n];
    } else if (idx < OFF_C2HD) {
        int j = idx - OFF_C2HE, kp = j / 128, n = j % 128;
        v0 = Wc2he[(2 * kp) * 128 + n]; v1 = Wc2he[(2 * kp + 1) * 128 + n];
    } else if (idx < OFF_ML) {
        int j = idx - OFF_C2HD, kp = j / 128, n = j % 128;
        v0 = Wc2hd[(2 * kp) * 128 + n]; v1 = Wc2hd[(2 * kp + 1) * 128 + n];
    } else if (idx < OFF_Z2H) {
        int j = idx - OFF_ML, kp = j / 64, n = j % 64;
        if (n < 32) { v0 = Wm[(2 * kp) * 32 + n];  v1 = Wm[(2 * kp + 1) * 32 + n]; }
        else        { v0 = Wlv[(2 * kp) * 32 + n - 32]; v1 = Wlv[(2 * kp + 1) * 32 + n - 32]; }
    } else if (idx < OFF_OUT) {
        int j = idx - OFF_Z2H, kp = j / 128, n = j % 128;
        v0 = Wz2h[(2 * kp) * 128 + n]; v1 = Wz2h[(2 * kp + 1) * 128 + n];
    } else {
        int j = idx - OFF_OUT, kp = j / 128, n = j % 128;
        v0 = Wout[(2 * kp) * 128 + n]; v1 = Wout[(2 * kp + 1) * 128 + n];
    }
    __nv_bfloat16 h0 = __float2bfloat16_rn(v0);
    __nv_bfloat16 h1 = __float2bfloat16_rn(v1);
    __nv_bfloat16 l0 = __float2bfloat16_rn(v0 - __bfloat162float(h0));
    __nv_bfloat16 l1 = __float2bfloat16_rn(v1 - __bfloat162float(h1));
    uint16_t u0, u1, w0, w1;
    memcpy(&u0, &h0, 2); memcpy(&u1, &h1, 2);
    memcpy(&w0, &l0, 2); memcpy(&w1, &l1, 2);
    g_WH32[idx] = (uint32_t)u0 | ((uint32_t)u1 << 16);
    g_WL32[idx] = (uint32_t)w0 | ((uint32_t)w1 << 16);
}

// ---------------- CSR aggregation, 2 float4 per thread ----------------
// thread handles chunks 2c,2c+1 of node i (C0 must be even so pairs don't straddle)
template<int C0, int C1, bool BIAS, int OM>
__global__ __launch_bounds__(256) void k_aggc(
    const float4* __restrict__ s0, const float4* __restrict__ s1,
    const float4* __restrict__ bias, float4* __restrict__ dst,
    __nv_bfloat16* __restrict__ dsth, __nv_bfloat16* __restrict__ dstl, int n)
{
    constexpr int CT  = C0 + C1;
    constexpr int TPN = CT / 2;
    int idx = blockIdx.x * 256 + threadIdx.x;
    if (idx >= n * TPN) return;
    int i = idx / TPN, c = (idx % TPN) * 2;

    const float4* __restrict__ base;
    int stride;
    if (C1 == 0 || c < C0) { base = s0 + c;        stride = C0; }
    else                   { base = s1 + (c - C0); stride = C1; }

    float d = g_dis[i];
    float w0 = d * d;
    float4 v0 = base[(size_t)i * stride];
    float4 v1 = base[(size_t)i * stride + 1];
    float4 a0, a1;
    a0.x = v0.x * w0; a0.y = v0.y * w0; a0.z = v0.z * w0; a0.w = v0.w * w0;
    a1.x = v1.x * w0; a1.y = v1.y * w0; a1.z = v1.z * w0; a1.w = v1.w * w0;

    int b = g_off[i], bend = g_off[i + 1];
    #pragma unroll 4
    for (int eix = b; eix < bend; eix++) {
        int   r = g_srows[eix];
        float w = g_senorm[eix];
        float4 u0 = base[(size_t)r * stride];
        float4 u1 = base[(size_t)r * stride + 1];
        a0.x += u0.x * w; a0.y += u0.y * w; a0.z += u0.z * w; a0.w += u0.w * w;
        a1.x += u1.x * w; a1.y += u1.y * w; a1.z += u1.z * w; a1.w += u1.w * w;
    }
    if (BIAS) {
        float4 b0 = bias[c], b1 = bias[c + 1];
        a0.x += b0.x; a0.y += b0.y; a0.z += b0.z; a0.w += b0.w;
        a1.x += b1.x; a1.y += b1.y; a1.z += b1.z; a1.w += b1.w;
    }
    if (OM == 0) {
        dst[(size_t)i * CT + c]     = a0;
        dst[(size_t)i * CT + c + 1] = a1;
    } else {
        uint4 hp, lp;
        __nv_bfloat162 t;
        #define SPLIT2(X, Y, HO, LO) { \
            t.x = __float2bfloat16_rn(X); t.y = __float2bfloat16_rn(Y); \
            HO = *(uint32_t*)&t; \
            __nv_bfloat162 tl; \
            tl.x = __float2bfloat16_rn((X) - __bfloat162float(t.x)); \
            tl.y = __float2bfloat16_rn((Y) - __bfloat162float(t.y)); \
            LO = *(uint32_t*)&tl; }
        SPLIT2(a0.x, a0.y, hp.x, lp.x);
        SPLIT2(a0.z, a0.w, hp.y, lp.y);
        SPLIT2(a1.x, a1.y, hp.z, lp.z);
        SPLIT2(a1.z, a1.w, hp.w, lp.w);
        #undef SPLIT2
        size_t o = ((size_t)i * CT + c) * 4;
        *(uint4*)&dsth[o] = hp;
        *(uint4*)&dstl[o] = lp;
    }
}

// ---------------- fused pass B: Agg(P)+bias, then reparameterize ----------------
__global__ __launch_bounds__(256) void k_aggB(
    const float4* __restrict__ P, const float4* __restrict__ noise,
    float4* __restrict__ oz, float4* __restrict__ om, float4* __restrict__ olv, int n)
{
    int idx = blockIdx.x * 256 + threadIdx.x;
    if (idx >= n * 8) return;
    int i = idx / 8, c = idx % 8;

    float d = g_dis[i];
    float w0 = d * d;
    float4 vm = P[(size_t)i * 16 + c];
    float4 vl = P[(size_t)i * 16 + c + 8];
    float4 am, al;
    am.x = vm.x * w0; am.y = vm.y * w0; am.z = vm.z * w0; am.w = vm.w * w0;
    al.x = vl.x * w0; al.y = vl.y * w0; al.z = vl.z * w0; al.w = vl.w * w0;

    int b = g_off[i], bend = g_off[i + 1];
    #pragma unroll 4
    for (int eix = b; eix < bend; eix++) {
        int   r = g_srows[eix];
        float w = g_senorm[eix];
        float4 um = P[(size_t)r * 16 + c];
        float4 ul = P[(size_t)r * 16 + c + 8];
        am.x += um.x * w; am.y += um.y * w; am.z += um.z * w; am.w += um.w * w;
        al.x += ul.x * w; al.y += ul.y * w; al.z += ul.z * w; al.w += ul.w * w;
    }
    const float4* bml4 = (const float4*)g_bml;
    float4 bm = bml4[c], blv = bml4[c + 8];
    am.x += bm.x;  am.y += bm.y;  am.z += bm.z;  am.w += bm.w;
    al.x += blv.x; al.y += blv.y; al.z += blv.z; al.w += blv.w;

    float4 nv = noise[idx];
    float4 zv;
    zv.x = nv.x * expf(0.5f * al.x) + am.x;
    zv.y = nv.y * expf(0.5f * al.y) + am.y;
    zv.z = nv.z * expf(0.5f * al.z) + am.z;
    zv.w = nv.w * expf(0.5f * al.w) + am.w;

    oz[idx]  = zv;
    om[idx]  = am;
    olv[idx] = al;
}

// ---------------- cp.async double-buffered split-bf16 tensor-core GEMM ----------------
// Optional dual-mode: gridDim.y==2 selects second weight/bias/output set (same A).
__device__ __forceinline__ void mma_bf16(float* d,
    uint32_t a0, uint32_t a1, uint32_t a2, uint32_t a3,
    uint32_t b0, uint32_t b1)
{
    asm volatile(
        "mma.sync.aligned.m16n8k16.row.col.f32.bf16.bf16.f32 "
        "{%0,%1,%2,%3}, {%4,%5,%6,%7}, {%8,%9}, {%0,%1,%2,%3};\n"
        : "+f"(d[0]), "+f"(d[1]), "+f"(d[2]), "+f"(d[3])
        : "r"(a0), "r"(a1), "r"(a2), "r"(a3), "r"(b0), "r"(b1));
}

template<int K, int NC, bool BIAS, bool TANH, bool SPLITOUT>
__global__ __launch_bounds__(256, 2) void k_gemm_cp(
    const uint32_t* __restrict__ Ah, const uint32_t* __restrict__ Al, int ldau,
    const uint32_t* __restrict__ Wh, const uint32_t* __restrict__ Wl,
    const float* __restrict__ bias,
    float* __restrict__ C, __nv_bfloat16* __restrict__ Ch, __nv_bfloat16* __restrict__ Cl,
    int ldc, int M,
    const uint32_t* Wh2, const uint32_t* Wl2, const float* bias2,
    __nv_bfloat16* Ch2, __nv_bfloat16* Cl2)
{
    constexpr int BM = 128;
    constexpr int PA = 20;
    constexpr int PW = NC + 8;
    constexpr int WN = NC / 4;
    constexpr int NJ = WN / 8;
    constexpr int NK = K / 32;
    constexpr int ASZ = BM * PA;
    constexpr int WSZ = 16 * PW;

    if (blockIdx.y == 1) {
        Wh = Wh2; Wl = Wl2; bias = bias2; Ch = Ch2; Cl = Cl2;
    }

    extern __shared__ uint32_t smem32[];
    uint32_t sb = smem_u32(smem32);

    int tid  = threadIdx.x;
    int lane = tid & 31;
    int wid  = tid >> 5;
    int warpM = wid >> 2, warpN = wid & 3;
    int wr0 = warpM * 64;
    int wc0 = warpN * WN;
    int g = lane >> 2, q = lane & 3;
    int m0 = blockIdx.x * BM;

    float acc[4][NJ][4];
    #pragma unroll
    for (int mi = 0; mi < 4; mi++)
        #pragma unroll
        for (int nj = 0; nj < NJ; nj++)
            #pragma unroll
            for (int t = 0; t < 4; t++) acc[mi][nj][t] = 0.0f;

    auto fill = [&](int ck, int b) {
        int kpb = ck * 16;
        uint32_t aH = sb + (uint32_t)((b * 2 + 0) * ASZ) * 4;
        uint32_t aL = sb + (uint32_t)((b * 2 + 1) * ASZ) * 4;
        uint32_t wH = sb + (uint32_t)(4 * ASZ + (b * 2 + 0) * WSZ) * 4;
        uint32_t wL = sb + (uint32_t)(4 * ASZ + (b * 2 + 1) * WSZ) * 4;
        #pragma unroll
        for (int f = tid; f < BM * 4; f += 256) {
            int r = f >> 2, seg = f & 3;
            int gr = m0 + r;
            uint32_t sz = (gr < M) ? 16u : 0u;
            size_t go = (size_t)gr * ldau + kpb + seg * 4;
            uint32_t so = (uint32_t)(r * PA + seg * 4) * 4;
            cp16(aH + so, Ah + go, sz);
            cp16(aL + so, Al + go, sz);
        }
        #pragma unroll
        for (int f = tid; f < 4 * NC; f += 256) {
            int kp2 = f / (NC / 4);
            int seg = f % (NC / 4);
            size_t go = (size_t)(kpb + kp2) * NC + seg * 4;
            uint32_t so = (uint32_t)(kp2 * PW + seg * 4) * 4;
            cp16(wH + so, Wh + go, 16u);
            cp16(wL + so, Wl + go, 16u);
        }
    };

    fill(0, 0);
    CP_COMMIT();

    for (int ck = 0; ck < NK; ck++) {
        if (ck + 1 < NK) fill(ck + 1, (ck + 1) & 1);
        CP_COMMIT();
        if (ck + 1 < NK) { CP_WAIT(1); } else { CP_WAIT(0); }
        __syncthreads();

        int b = ck & 1;
        const uint32_t* sAh = smem32 + (b * 2 + 0) * ASZ;
        const uint32_t* sAl = smem32 + (b * 2 + 1) * ASZ;
        const uint32_t* sWh = smem32 + 4 * ASZ + (b * 2 + 0) * WSZ;
        const uint32_t* sWl = smem32 + 4 * ASZ + (b * 2 + 1) * WSZ;

        #pragma unroll
        for (int s = 0; s < 2; s++) {
            uint32_t bh[NJ][2], bl[NJ][2];
            int kp0 = s * 8 + q;
            #pragma unroll
            for (int nj = 0; nj < NJ; nj++) {
                int nn = wc0 + nj * 8 + g;
                bh[nj][0] = sWh[kp0 * PW + nn];
                bh[nj][1] = sWh[(kp0 + 4) * PW + nn];
                bl[nj][0] = sWl[kp0 * PW + nn];
                bl[nj][1] = sWl[(kp0 + 4) * PW + nn];
            }
            #pragma unroll
            for (int mi = 0; mi < 4; mi++) {
                int r = wr0 + mi * 16 + g;
                uint32_t ah0 = sAh[r * PA + kp0];
                uint32_t ah1 = sAh[(r + 8) * PA + kp0];
                uint32_t ah2 = sAh[r * PA + kp0 + 4];
                uint32_t ah3 = sAh[(r + 8) * PA + kp0 + 4];
                uint32_t al0 = sAl[r * PA + kp0];
                uint32_t al1 = sAl[(r + 8) * PA + kp0];
                uint32_t al2 = sAl[r * PA + kp0 + 4];
                uint32_t al3 = sAl[(r + 8) * PA + kp0 + 4];
                #pragma unroll
                for (int nj = 0; nj < NJ; nj++) {
                    mma_bf16(acc[mi][nj], ah0, ah1, ah2, ah3, bh[nj][0], bh[nj][1]);
                    mma_bf16(acc[mi][nj], ah0, ah1, ah2, ah3, bl[nj][0], bl[nj][1]);
                    mma_bf16(acc[mi][nj], al0, al1, al2, al3, bh[nj][0], bh[nj][1]);
                }
            }
        }
        __syncthreads();
    }

    // ---- epilogue ----
    #pragma unroll
    for (int mi = 0; mi < 4; mi++) {
        #pragma unroll
        for (int nj = 0; nj < NJ; nj++) {
            int c  = wc0 + nj * 8 + 2 * q;
            float b0v = 0.f, b1v = 0.f;
            if (BIAS) { b0v = bias[c]; b1v = bias[c + 1]; }
            int r0 = m0 + wr0 + mi * 16 + g;
            float v0 = acc[mi][nj][0] + b0v;
            float v1 = acc[mi][nj][1] + b1v;
            float v2 = acc[mi][nj][2] + b0v;
            float v3 = acc[mi][nj][3] + b1v;
            if (TANH) { v0 = tanhf(v0); v1 = tanhf(v1); v2 = tanhf(v2); v3 = tanhf(v3); }
            if (SPLITOUT) {
                if (r0 < M) {
                    __nv_bfloat162 hh, ll;
                    hh.x = __float2bfloat16_rn(v0); hh.y = __float2bfloat16_rn(v1);
                    ll.x = __float2bfloat16_rn(v0 - __bfloat162float(hh.x));
                    ll.y = __float2bfloat16_rn(v1 - __bfloat162float(hh.y));
                    *(uint32_t*)&Ch[(size_t)r0 * ldc + c] = *(uint32_t*)&hh;
                    *(uint32_t*)&Cl[(size_t)r0 * ldc + c] = *(uint32_t*)&ll;
                }
                if (r0 + 8 < M) {
                    __nv_bfloat162 hh, ll;
                    hh.x = __float2bfloat16_rn(v2); hh.y = __float2bfloat16_rn(v3);
                    ll.x = __float2bfloat16_rn(v2 - __bfloat162float(hh.x));
                    ll.y = __float2bfloat16_rn(v3 - __bfloat162float(hh.y));
                    *(uint32_t*)&Ch[(size_t)(r0 + 8) * ldc + c] = *(uint32_t*)&hh;
                    *(uint32_t*)&Cl[(size_t)(r0 + 8) * ldc + c] = *(uint32_t*)&ll;
                }
            } else {
                if (r0 < M) {
                    float2 o; o.x = v0; o.y = v1;
                    *(float2*)&C[(size_t)r0 * ldc + c] = o;
                }
                if (r0 + 8 < M) {
                    float2 o; o.x = v2; o.y = v3;
                    *(float2*)&C[(size_t)(r0 + 8) * ldc + c] = o;
                }
            }
        }
    }
}

// ---------------- launch ----------------
static inline int cdiv(int a, int b) { return (a + b - 1) / b; }

extern "C" void kernel_launch(void* const* d_in, const int* in_sizes, int n_in,
                              void* d_out, int out_size) {
    const float* feature   = (const float*)d_in[0];
    const float* condition = (const float*)d_in[1];
    const float* noise     = (const float*)d_in[2];
    const float* W_f2h     = (const float*)d_in[3];
    const float* b_f2h     = (const float*)d_in[4];
    const float* W_c2h_e   = (const float*)d_in[5];
    const float* b_c2h_e   = (const float*)d_in[6];
    const float* W_mean    = (const float*)d_in[7];
    const float* b_mean    = (const float*)d_in[8];
    const float* W_logvar  = (const float*)d_in[9];
    const float* b_logvar  = (const float*)d_in[10];
    const float* W_z2h     = (const float*)d_in[11];
    const float* b_z2h     = (const float*)d_in[12];
    const float* W_c2h_d   = (const float*)d_in[13];
    const float* b_c2h_d   = (const float*)d_in[14];
    const float* W_out     = (const float*)d_in[15];
    const float* b_out     = (const float*)d_in[16];
    const void*  eidx      = d_in[17];

    int n = in_sizes[0] / 128;
    int e = in_sizes[17] / 2;

    float* oz  = (float*)d_out;
    float* om  = oz  + (size_t)n * 32;
    float* olv = om  + (size_t)n * 32;
    float* oo  = olv + (size_t)n * 32;

    void *pP, *pO, *pDeg, *pCnt;
    void *pAfcH, *pAfcL, *pH2H, *pH2L, *pHDH, *pHDL, *pAzH, *pAzL, *pWH, *pWL;
    cudaGetSymbolAddress(&pP,    g_P);
    cudaGetSymbolAddress(&pO,    g_O);
    cudaGetSymbolAddress(&pDeg,  g_deg);
    cudaGetSymbolAddress(&pCnt,  g_cnt);
    cudaGetSymbolAddress(&pAfcH, g_AfcH);
    cudaGetSymbolAddress(&pAfcL, g_AfcL);
    cudaGetSymbolAddress(&pH2H,  g_H2H);
    cudaGetSymbolAddress(&pH2L,  g_H2L);
    cudaGetSymbolAddress(&pHDH,  g_HDH);
    cudaGetSymbolAddress(&pHDL,  g_HDL);
    cudaGetSymbolAddress(&pAzH,  g_AzH);
    cudaGetSymbolAddress(&pAzL,  g_AzL);
    cudaGetSymbolAddress(&pWH,   g_WH32);
    cudaGetSymbolAddress(&pWL,   g_WL32);
    float* P = (float*)pP;
    float* O = (float*)pO;
    __nv_bfloat16* AfcH = (__nv_bfloat16*)pAfcH;
    __nv_bfloat16* AfcL = (__nv_bfloat16*)pAfcL;
    __nv_bfloat16* H2H  = (__nv_bfloat16*)pH2H;
    __nv_bfloat16* H2L  = (__nv_bfloat16*)pH2L;
    __nv_bfloat16* HDH  = (__nv_bfloat16*)pHDH;
    __nv_bfloat16* HDL  = (__nv_bfloat16*)pHDL;
    __nv_bfloat16* AzH  = (__nv_bfloat16*)pAzH;
    __nv_bfloat16* AzL  = (__nv_bfloat16*)pAzL;
    uint32_t* WH = (uint32_t*)pWH;
    uint32_t* WL = (uint32_t*)pWL;

    const int SM128 = (4 * 128 * 20 + 4 * 16 * (128 + 8)) * 4;   // 75776
    const int SM64  = (4 * 128 * 20 + 4 * 16 * (64  + 8)) * 4;   // 59392
    cudaFuncSetAttribute(k_gemm_cp<128, 128, true,  true,  true >, cudaFuncAttributeMaxDynamicSharedMemorySize, SM128);
    cudaFuncSetAttribute(k_gemm_cp<64,  128, true,  true,  true >, cudaFuncAttributeMaxDynamicSharedMemorySize, SM128);
    cudaFuncSetAttribute(k_gemm_cp<256, 64,  false, false, false>, cudaFuncAttributeMaxDynamicSharedMemorySize, SM64);
    cudaFuncSetAttribute(k_gemm_cp<32,  128, true,  true,  true >, cudaFuncAttributeMaxDynamicSharedMemorySize, SM128);
    cudaFuncSetAttribute(k_gemm_cp<256, 128, false, false, false>, cudaFuncAttributeMaxDynamicSharedMemorySize, SM128);

    int gg = cdiv(n, 128);

    // ---- fused CSR build (kernel 1) ----
    cudaMemsetAsync(pDeg, 0, (size_t)n * sizeof(int));
    cudaMemsetAsync(pCnt, 0, sizeof(unsigned));
    k_csr<<<NB, 256>>>(eidx, e, n);

    // Pass A -> Afc planes (kernel 2)
    k_aggc<32, 16, false, 1><<<cdiv(n * 24, 256), 256>>>(
        (const float4*)feature, (const float4*)condition, nullptr,
        nullptr, AfcH, AfcL, n);

    // weight pre-pack (kernel 3)
    k_packw<<<cdiv(W_TOTAL32, 256), 256>>>(W_f2h, W_c2h_e, W_c2h_d,
                                           W_mean, W_logvar, W_z2h, W_out,
                                           b_mean, b_logvar);

    // Encoder projections (kernel 4 = f2h GEMM <- profiled)
    k_gemm_cp<128, 128, true, true, true><<<gg, 256, SM128>>>(
        (const uint32_t*)AfcH, (const uint32_t*)AfcL, 96,
        WH + OFF_F2H, WL + OFF_F2H, b_f2h,
        nullptr, H2H, H2L, 256, n,
        nullptr, nullptr, nullptr, nullptr, nullptr);

    // c2h encoder + decoder halves merged into one dual launch
    {
        dim3 grid(gg, 2);
        k_gemm_cp<64, 128, true, true, true><<<grid, 256, SM128>>>(
            (const uint32_t*)AfcH + 64, (const uint32_t*)AfcL + 64, 96,
            WH + OFF_C2HE, WL + OFF_C2HE, b_c2h_e,
            nullptr, H2H + 128, H2L + 128, 256, n,
            WH + OFF_C2HD, WL + OFF_C2HD, b_c2h_d,
            HDH + 128, HDL + 128);
    }

    // mean+logvar fused projection -> fp32 P
    k_gemm_cp<256, 64, false, false, false><<<gg, 256, SM64>>>(
        (const uint32_t*)H2H, (const uint32_t*)H2L, 128,
        WH + OFF_ML, WL + OFF_ML, nullptr,
        P, nullptr, nullptr, 64, n,
        nullptr, nullptr, nullptr, nullptr, nullptr);

    // Pass B fused with reparameterization
    k_aggB<<<cdiv(n * 8, 256), 256>>>((const float4*)P, (const float4*)noise,
                                      (float4*)oz, (float4*)om, (float4*)olv, n);

    // Pass C: Az = Agg(z) -> planes
    k_aggc<8, 0, false, 1><<<cdiv(n * 4, 256), 256>>>(
        (const float4*)oz, nullptr, nullptr, nullptr, AzH, AzL, n);

    // Decoder
    k_gemm_cp<32, 128, true, true, true><<<gg, 256, SM128>>>(
        (const uint32_t*)AzH, (const uint32_t*)AzL, 16,
        WH + OFF_Z2H, WL + OFF_Z2H, b_z2h,
        nullptr, HDH, HDL, 256, n,
        nullptr, nullptr, nullptr, nullptr, nullptr);
    k_gemm_cp<256, 128, false, false, false><<<gg, 256, SM128>>>(
        (const uint32_t*)HDH, (const uint32_t*)HDL, 128,
        WH + OFF_OUT, WL + OFF_OUT, nullptr,
        O, nullptr, nullptr, 128, n,
        nullptr, nullptr, nullptr, nullptr, nullptr);

    // Pass D: out = Agg(O) + b_out (fp32)
    k_aggc<32, 0, true, 0><<<cdiv(n * 16, 256), 256>>>(
        (const float4*)O, nullptr, (const float4*)b_out, (float4*)oo,
        nullptr, nullptr, n);
}

// round 16
// speedup vs baseline: 1.0516x; 1.0516x over previous
#include <cuda_runtime.h>
#include <cuda_bf16.h>
#include <math.h>
#include <stdint.h>

#define NN 50000
#define EE 800000
#define NB 296          // resident blocks for fused CSR kernel (148 SMs x 2)

// packed-weight offsets in uint32 (bf162-pair) units, layout [K/2][NC]
#define OFF_F2H   0
#define OFF_C2HE  8192
#define OFF_C2HD  12288
#define OFF_ML    16384
#define OFF_Z2H   24576
#define OFF_OUT   26624
#define W_TOTAL32 43008

// ---------------- scratch (static __device__, no runtime allocation) ----------------
__device__ float g_dis[NN];
__device__ int   g_deg[NN];
__device__ int   g_off[NN + 1];
__device__ int   g_cur[NN];
__device__ int   g_rows[EE];
__device__ int   g_cols[EE];
__device__ int   g_srows[EE];
__device__ float g_senorm[EE];
__device__ float g_P  [NN * 64];
__device__ float g_O  [NN * 128];
__device__ float g_bml[64];
__device__ __nv_bfloat16 g_AfcH[NN * 192], g_AfcL[NN * 192];
__device__ __nv_bfloat16 g_H2H [NN * 256], g_H2L [NN * 256];
__device__ __nv_bfloat16 g_HDH [NN * 256], g_HDL [NN * 256];
__device__ __nv_bfloat16 g_AzH [NN * 32],  g_AzL [NN * 32];
__device__ uint32_t g_WH32[W_TOTAL32], g_WL32[W_TOTAL32];
__device__ unsigned g_cnt;
__device__ int   g_part[512];

// ---------------- helpers ----------------
__device__ __forceinline__ uint32_t smem_u32(const void* p) {
    uint32_t a;
    asm("{ .reg .u64 t; cvta.to.shared.u64 t, %1; cvt.u32.u64 %0, t; }" : "=r"(a) : "l"(p));
    return a;
}
__device__ __forceinline__ void cp16(uint32_t dst, const void* src, uint32_t sz) {
    asm volatile("cp.async.ca.shared.global [%0], [%1], 16, %2;"
                 :: "r"(dst), "l"(__cvta_generic_to_global(src)), "r"(sz) : "memory");
}
#define CP_COMMIT() asm volatile("cp.async.commit_group;" ::: "memory")
#define CP_WAIT(N)  asm volatile("cp.async.wait_group %0;" :: "n"(N) : "memory")

// software grid barrier (all blocks co-resident)
__device__ __forceinline__ void gbar(unsigned step) {
    __syncthreads();
    if (threadIdx.x == 0) {
        __threadfence();
        atomicAdd(&g_cnt, 1u);
        unsigned target = step * gridDim.x;
        while (*(volatile unsigned*)&g_cnt < target) { }
        __threadfence();
    }
    __syncthreads();
}

// ---------------- fused CSR build ----------------
__global__ __launch_bounds__(256) void k_csr(const void* p, int e, int n) {
    int tid = threadIdx.x, bid = blockIdx.x;
    int gsz = gridDim.x * 256;
    int gi  = bid * 256 + tid;
    __shared__ int sh[256];

    const long long* q64 = (const long long*)p;
    long long probe = 0;
    if (gi < e) probe = q64[gi];
    int okl = (probe >= 0 && probe < (long long)n) ? 1 : 0;
    int is64 = __syncthreads_and(okl);

    for (int i = gi; i < e; i += gsz) {
        int r, c;
        if (is64) { r = (int)q64[i]; c = (int)q64[e + i]; }
        else { const int* q32 = (const int*)p; r = q32[i]; c = q32[e + i]; }
        g_rows[i] = r;
        g_cols[i] = c;
        atomicAdd(&g_deg[c], 1);
    }
    gbar(1);

    int chunk = (n + gridDim.x - 1) / gridDim.x;
    int s  = bid * chunk;
    int en = s + chunk; if (en > n) en = n;
    {
        int sum = 0;
        for (int i = s + tid; i < en; i += 256) sum += g_deg[i];
        sh[tid] = sum;
        __syncthreads();
        for (int o = 128; o > 0; o >>= 1) {
            if (tid < o) sh[tid] += sh[tid + o];
            __syncthreads();
        }
        if (tid == 0) g_part[bid] = sh[0];
    }
    gbar(2);

    int base;
    {
        int b = 0;
        for (int i = tid; i < bid; i += 256) b += g_part[i];
        __syncthreads();
        sh[tid] = b;
        __syncthreads();
        for (int o = 128; o > 0; o >>= 1) {
            if (tid < o) sh[tid] += sh[tid + o];
            __syncthreads();
        }
        base = sh[0];
        __syncthreads();
    }

    {
        int i = s + tid;
        int live = (tid < en - s);
        int d = live ? g_deg[i] : 0;
        sh[tid] = d;
        __syncthreads();
        for (int o = 1; o < 256; o <<= 1) {
            int v = (tid >= o) ? sh[tid - o] : 0;
            __syncthreads();
            sh[tid] += v;
            __syncthreads();
        }
        int excl = base + sh[tid] - d;
        if (live) {
            g_off[i] = excl;
            g_cur[i] = excl;
            g_dis[i] = rsqrtf((float)d + 1.0f);
        }
        if (bid == gridDim.x - 1 && tid == 0) g_off[n] = e;
    }
    gbar(3);

    for (int i = gi; i < e; i += gsz) {
        int r = g_rows[i], c = g_cols[i];
        int pos = atomicAdd(&g_cur[c], 1);
        g_srows[pos]  = r;
        g_senorm[pos] = g_dis[r] * g_dis[c];
    }
}

// ---------------- weight pre-pack: fp32 -> bf162-pair hi/lo planes, [K/2][NC] ----------------
__global__ void k_packw(const float* __restrict__ Wf2h, const float* __restrict__ Wc2he,
                        const float* __restrict__ Wc2hd, const float* __restrict__ Wm,
                        const float* __restrict__ Wlv, const float* __restrict__ Wz2h,
                        const float* __restrict__ Wout,
                        const float* __restrict__ bm, const float* __restrict__ bl) {
    int idx = blockIdx.x * 256 + threadIdx.x;
    if (idx < 64) g_bml[idx] = (idx < 32) ? bm[idx] : bl[idx - 32];
    if (idx >= W_TOTAL32) return;
    float v0, v1;
    if (idx < OFF_C2HE) {
        int j = idx, kp = j / 128, n = j % 128;
        v0 = Wf2h[(2 * kp) * 128 + n]; v1 = Wf2h[(2 * kp + 1) * 128 + n];
    } else if (idx < OFF_C2HD) {
        int j = idx - OFF_C2HE, kp = j / 128, n = j % 128;
        v0 = Wc2he[(2 * kp) * 128 + n]; v1 = Wc2he[(2 * kp + 1) * 128 + n];
    } else if (idx < OFF_ML) {
        int j = idx - OFF_C2HD, kp = j / 128, n = j % 128;
        v0 = Wc2hd[(2 * kp) * 128 + n]; v1 = Wc2hd[(2 * kp + 1) * 128 + n];
    } else if (idx < OFF_Z2H) {
        int j = idx - OFF_ML, kp = j / 64, n = j % 64;
        if (n < 32) { v0 = Wm[(2 * kp) * 32 + n];  v1 = Wm[(2 * kp + 1) * 32 + n]; }
        else        { v0 = Wlv[(2 * kp) * 32 + n - 32]; v1 = Wlv[(2 * kp + 1) * 32 + n - 32]; }
    } else if (idx < OFF_OUT) {
        int j = idx - OFF_Z2H, kp = j / 128, n = j % 128;
        v0 = Wz2h[(2 * kp) * 128 + n]; v1 = Wz2h[(2 * kp + 1) * 128 + n];
    } else {
        int j = idx - OFF_OUT, kp = j / 128, n = j % 128;
        v0 = Wout[(2 * kp) * 128 + n]; v1 = Wout[(2 * kp + 1) * 128 + n];
    }
    __nv_bfloat16 h0 = __float2bfloat16_rn(v0);
    __nv_bfloat16 h1 = __float2bfloat16_rn(v1);
    __nv_bfloat16 l0 = __float2bfloat16_rn(v0 - __bfloat162float(h0));
    __nv_bfloat16 l1 = __float2bfloat16_rn(v1 - __bfloat162float(h1));
    uint16_t u0, u1, w0, w1;
    memcpy(&u0, &h0, 2); memcpy(&u1, &h1, 2);
    memcpy(&w0, &l0, 2); memcpy(&w1, &l1, 2);
    g_WH32[idx] = (uint32_t)u0 | ((uint32_t)u1 << 16);
    g_WL32[idx] = (uint32_t)w0 | ((uint32_t)w1 << 16);
}

// ---------------- CSR aggregation (OM: 0 fp32 out, 1 bf16 hi/lo split out) ----------------
template<int C0, int C1, bool BIAS, int OM>
__global__ __launch_bounds__(256) void k_aggc(
    const float4* __restrict__ s0, const float4* __restrict__ s1,
    const float4* __restrict__ bias, float4* __restrict__ dst,
    __nv_bfloat16* __restrict__ dsth, __nv_bfloat16* __restrict__ dstl, int n)
{
    constexpr int CT = C0 + C1;
    int idx = blockIdx.x * 256 + threadIdx.x;
    if (idx >= n * CT) return;
    int i = idx / CT, c = idx % CT;

    const float4* __restrict__ base;
    int stride;
    if (C1 == 0 || c < C0) { base = s0 + c;        stride = C0; }
    else                   { base = s1 + (c - C0); stride = C1; }

    float d = g_dis[i];
    float w0 = d * d;
    float4 v = base[(size_t)i * stride];
    float4 acc;
    acc.x = v.x * w0; acc.y = v.y * w0; acc.z = v.z * w0; acc.w = v.w * w0;

    int b = g_off[i], bend = g_off[i + 1];
    #pragma unroll 4
    for (int eix = b; eix < bend; eix++) {
        int   r = g_srows[eix];
        float w = g_senorm[eix];
        float4 u = base[(size_t)r * stride];
        acc.x += u.x * w; acc.y += u.y * w; acc.z += u.z * w; acc.w += u.w * w;
    }
    if (BIAS) {
        float4 bb = bias[c];
        acc.x += bb.x; acc.y += bb.y; acc.z += bb.z; acc.w += bb.w;
    }
    if (OM == 0) {
        dst[(size_t)i * CT + c] = acc;
    } else {
        __nv_bfloat162 h01, h23, l01, l23;
        h01.x = __float2bfloat16_rn(acc.x);
        h01.y = __float2bfloat16_rn(acc.y);
        h23.x = __float2bfloat16_rn(acc.z);
        h23.y = __float2bfloat16_rn(acc.w);
        l01.x = __float2bfloat16_rn(acc.x - __bfloat162float(h01.x));
        l01.y = __float2bfloat16_rn(acc.y - __bfloat162float(h01.y));
        l23.x = __float2bfloat16_rn(acc.z - __bfloat162float(h23.x));
        l23.y = __float2bfloat16_rn(acc.w - __bfloat162float(h23.y));
        size_t o = ((size_t)i * CT + c) * 4;
        uint2 hp, lp;
        hp.x = *(uint32_t*)&h01; hp.y = *(uint32_t*)&h23;
        lp.x = *(uint32_t*)&l01; lp.y = *(uint32_t*)&l23;
        *(uint2*)&dsth[o] = hp;
        *(uint2*)&dstl[o] = lp;
    }
}

// ---------------- fused pass B: Agg(P)+bias, then reparameterize ----------------
__global__ __launch_bounds__(256) void k_aggB(
    const float4* __restrict__ P, const float4* __restrict__ noise,
    float4* __restrict__ oz, float4* __restrict__ om, float4* __restrict__ olv, int n)
{
    int idx = blockIdx.x * 256 + threadIdx.x;
    if (idx >= n * 8) return;
    int i = idx / 8, c = idx % 8;

    float d = g_dis[i];
    float w0 = d * d;
    float4 vm = P[(size_t)i * 16 + c];
    float4 vl = P[(size_t)i * 16 + c + 8];
    float4 am, al;
    am.x = vm.x * w0; am.y = vm.y * w0; am.z = vm.z * w0; am.w = vm.w * w0;
    al.x = vl.x * w0; al.y = vl.y * w0; al.z = vl.z * w0; al.w = vl.w * w0;

    int b = g_off[i], bend = g_off[i + 1];
    #pragma unroll 4
    for (int eix = b; eix < bend; eix++) {
        int   r = g_srows[eix];
        float w = g_senorm[eix];
        float4 um = P[(size_t)r * 16 + c];
        float4 ul = P[(size_t)r * 16 + c + 8];
        am.x += um.x * w; am.y += um.y * w; am.z += um.z * w; am.w += um.w * w;
        al.x += ul.x * w; al.y += ul.y * w; al.z += ul.z * w; al.w += ul.w * w;
    }
    const float4* bml4 = (const float4*)g_bml;
    float4 bm = bml4[c], blv = bml4[c + 8];
    am.x += bm.x;  am.y += bm.y;  am.z += bm.z;  am.w += bm.w;
    al.x += blv.x; al.y += blv.y; al.z += blv.z; al.w += blv.w;

    float4 nv = noise[idx];
    float4 zv;
    zv.x = nv.x * expf(0.5f * al.x) + am.x;
    zv.y = nv.y * expf(0.5f * al.y) + am.y;
    zv.z = nv.z * expf(0.5f * al.z) + am.z;
    zv.w = nv.w * expf(0.5f * al.w) + am.w;

    oz[idx]  = zv;
    om[idx]  = am;
    olv[idx] = al;
}

// ---------------- cp.async double-buffered split-bf16 tensor-core GEMM ----------------
// Optional dual-mode: gridDim.y==2 selects second weight/bias/output set (same A).
__device__ __forceinline__ void mma_bf16(float* d,
    uint32_t a0, uint32_t a1, uint32_t a2, uint32_t a3,
    uint32_t b0, uint32_t b1)
{
    asm volatile(
        "mma.sync.aligned.m16n8k16.row.col.f32.bf16.bf16.f32 "
        "{%0,%1,%2,%3}, {%4,%5,%6,%7}, {%8,%9}, {%0,%1,%2,%3};\n"
        : "+f"(d[0]), "+f"(d[1]), "+f"(d[2]), "+f"(d[3])
        : "r"(a0), "r"(a1), "r"(a2), "r"(a3), "r"(b0), "r"(b1));
}

template<int K, int NC, bool BIAS, bool TANH, bool SPLITOUT>
__global__ __launch_bounds__(256, 2) void k_gemm_cp(
    const uint32_t* __restrict__ Ah, const uint32_t* __restrict__ Al, int ldau,
    const uint32_t* __restrict__ Wh, const uint32_t* __restrict__ Wl,
    const float* __restrict__ bias,
    float* __restrict__ C, __nv_bfloat16* __restrict__ Ch, __nv_bfloat16* __restrict__ Cl,
    int ldc, int M,
    const uint32_t* Wh2, const uint32_t* Wl2, const float* bias2,
    __nv_bfloat16* Ch2, __nv_bfloat16* Cl2)
{
    constexpr int BM = 128;
    constexpr int PA = 20;
    constexpr int PW = NC + 8;
    constexpr int WN = NC / 4;
    constexpr int NJ = WN / 8;
    constexpr int NK = K / 32;
    constexpr int ASZ = BM * PA;
    constexpr int WSZ = 16 * PW;

    if (blockIdx.y == 1) {
        Wh = Wh2; Wl = Wl2; bias = bias2; Ch = Ch2; Cl = Cl2;
    }

    extern __shared__ uint32_t smem32[];
    uint32_t sb = smem_u32(smem32);

    int tid  = threadIdx.x;
    int lane = tid & 31;
    int wid  = tid >> 5;
    int warpM = wid >> 2, warpN = wid & 3;
    int wr0 = warpM * 64;
    int wc0 = warpN * WN;
    int g = lane >> 2, q = lane & 3;
    int m0 = blockIdx.x * BM;

    float acc[4][NJ][4];
    #pragma unroll
    for (int mi = 0; mi < 4; mi++)
        #pragma unroll
        for (int nj = 0; nj < NJ; nj++)
            #pragma unroll
            for (int t = 0; t < 4; t++) acc[mi][nj][t] = 0.0f;

    auto fill = [&](int ck, int b) {
        int kpb = ck * 16;
        uint32_t aH = sb + (uint32_t)((b * 2 + 0) * ASZ) * 4;
        uint32_t aL = sb + (uint32_t)((b * 2 + 1) * ASZ) * 4;
        uint32_t wH = sb + (uint32_t)(4 * ASZ + (b * 2 + 0) * WSZ) * 4;
        uint32_t wL = sb + (uint32_t)(4 * ASZ + (b * 2 + 1) * WSZ) * 4;
        #pragma unroll
        for (int f = tid; f < BM * 4; f += 256) {
            int r = f >> 2, seg = f & 3;
            int gr = m0 + r;
            uint32_t sz = (gr < M) ? 16u : 0u;
            size_t go = (size_t)gr * ldau + kpb + seg * 4;
            uint32_t so = (uint32_t)(r * PA + seg * 4) * 4;
            cp16(aH + so, Ah + go, sz);
            cp16(aL + so, Al + go, sz);
        }
        #pragma unroll
        for (int f = tid; f < 4 * NC; f += 256) {
            int kp2 = f / (NC / 4);
            int seg = f % (NC / 4);
            size_t go = (size_t)(kpb + kp2) * NC + seg * 4;
            uint32_t so = (uint32_t)(kp2 * PW + seg * 4) * 4;
            cp16(wH + so, Wh + go, 16u);
            cp16(wL + so, Wl + go, 16u);
        }
    };

    fill(0, 0);
    CP_COMMIT();

    for (int ck = 0; ck < NK; ck++) {
        if (ck + 1 < NK) fill(ck + 1, (ck + 1) & 1);
        CP_COMMIT();
        if (ck + 1 < NK) { CP_WAIT(1); } else { CP_WAIT(0); }
        __syncthreads();

        int b = ck & 1;
        const uint32_t* sAh = smem32 + (b * 2 + 0) * ASZ;
        const uint32_t* sAl = smem32 + (b * 2 + 1) * ASZ;
        const uint32_t* sWh = smem32 + 4 * ASZ + (b * 2 + 0) * WSZ;
        const uint32_t* sWl = smem32 + 4 * ASZ + (b * 2 + 1) * WSZ;

        #pragma unroll
        for (int s = 0; s < 2; s++) {
            uint32_t bh[NJ][2], bl[NJ][2];
            int kp0 = s * 8 + q;
            #pragma unroll
            for (int nj = 0; nj < NJ; nj++) {
                int nn = wc0 + nj * 8 + g;
                bh[nj][0] = sWh[kp0 * PW + nn];
                bh[nj][1] = sWh[(kp0 + 4) * PW + nn];
                bl[nj][0] = sWl[kp0 * PW + nn];
                bl[nj][1] = sWl[(kp0 + 4) * PW + nn];
            }
            #pragma unroll
            for (int mi = 0; mi < 4; mi++) {
                int r = wr0 + mi * 16 + g;
                uint32_t ah0 = sAh[r * PA + kp0];
                uint32_t ah1 = sAh[(r + 8) * PA + kp0];
                uint32_t ah2 = sAh[r * PA + kp0 + 4];
                uint32_t ah3 = sAh[(r + 8) * PA + kp0 + 4];
                uint32_t al0 = sAl[r * PA + kp0];
                uint32_t al1 = sAl[(r + 8) * PA + kp0];
                uint32_t al2 = sAl[r * PA + kp0 + 4];
                uint32_t al3 = sAl[(r + 8) * PA + kp0 + 4];
                #pragma unroll
                for (int nj = 0; nj < NJ; nj++) {
                    mma_bf16(acc[mi][nj], ah0, ah1, ah2, ah3, bh[nj][0], bh[nj][1]);
                    mma_bf16(acc[mi][nj], ah0, ah1, ah2, ah3, bl[nj][0], bl[nj][1]);
                    mma_bf16(acc[mi][nj], al0, al1, al2, al3, bh[nj][0], bh[nj][1]);
                }
            }
        }
        __syncthreads();
    }

    // ---- epilogue ----
    #pragma unroll
    for (int mi = 0; mi < 4; mi++) {
        #pragma unroll
        for (int nj = 0; nj < NJ; nj++) {
            int c  = wc0 + nj * 8 + 2 * q;
            float b0v = 0.f, b1v = 0.f;
            if (BIAS) { b0v = bias[c]; b1v = bias[c + 1]; }
            int r0 = m0 + wr0 + mi * 16 + g;
            float v0 = acc[mi][nj][0] + b0v;
            float v1 = acc[mi][nj][1] + b1v;
            float v2 = acc[mi][nj][2] + b0v;
            float v3 = acc[mi][nj][3] + b1v;
            if (TANH) { v0 = tanhf(v0); v1 = tanhf(v1); v2 = tanhf(v2); v3 = tanhf(v3); }
            if (SPLITOUT) {
                if (r0 < M) {
                    __nv_bfloat162 hh, ll;
                    hh.x = __float2bfloat16_rn(v0); hh.y = __float2bfloat16_rn(v1);
                    ll.x = __float2bfloat16_rn(v0 - __bfloat162float(hh.x));
                    ll.y = __float2bfloat16_rn(v1 - __bfloat162float(hh.y));
                    *(uint32_t*)&Ch[(size_t)r0 * ldc + c] = *(uint32_t*)&hh;
                    *(uint32_t*)&Cl[(size_t)r0 * ldc + c] = *(uint32_t*)&ll;
                }
                if (r0 + 8 < M) {
                    __nv_bfloat162 hh, ll;
                    hh.x = __float2bfloat16_rn(v2); hh.y = __float2bfloat16_rn(v3);
                    ll.x = __float2bfloat16_rn(v2 - __bfloat162float(hh.x));
                    ll.y = __float2bfloat16_rn(v3 - __bfloat162float(hh.y));
                    *(uint32_t*)&Ch[(size_t)(r0 + 8) * ldc + c] = *(uint32_t*)&hh;
                    *(uint32_t*)&Cl[(size_t)(r0 + 8) * ldc + c] = *(uint32_t*)&ll;
                }
            } else {
                if (r0 < M) {
                    float2 o; o.x = v0; o.y = v1;
                    *(float2*)&C[(size_t)r0 * ldc + c] = o;
                }
                if (r0 + 8 < M) {
                    float2 o; o.x = v2; o.y = v3;
                    *(float2*)&C[(size_t)(r0 + 8) * ldc + c] = o;
                }
            }
        }
    }
}

// ---------------- launch ----------------
static inline int cdiv(int a, int b) { return (a + b - 1) / b; }

extern "C" void kernel_launch(void* const* d_in, const int* in_sizes, int n_in,
                              void* d_out, int out_size) {
    const float* feature   = (const float*)d_in[0];
    const float* condition = (const float*)d_in[1];
    const float* noise     = (const float*)d_in[2];
    const float* W_f2h     = (const float*)d_in[3];
    const float* b_f2h     = (const float*)d_in[4];
    const float* W_c2h_e   = (const float*)d_in[5];
    const float* b_c2h_e   = (const float*)d_in[6];
    const float* W_mean    = (const float*)d_in[7];
    const float* b_mean    = (const float*)d_in[8];
    const float* W_logvar  = (const float*)d_in[9];
    const float* b_logvar  = (const float*)d_in[10];
    const float* W_z2h     = (const float*)d_in[11];
    const float* b_z2h     = (const float*)d_in[12];
    const float* W_c2h_d   = (const float*)d_in[13];
    const float* b_c2h_d   = (const float*)d_in[14];
    const float* W_out     = (const float*)d_in[15];
    const float* b_out     = (const float*)d_in[16];
    const void*  eidx      = d_in[17];

    int n = in_sizes[0] / 128;
    int e = in_sizes[17] / 2;

    float* oz  = (float*)d_out;
    float* om  = oz  + (size_t)n * 32;
    float* olv = om  + (size_t)n * 32;
    float* oo  = olv + (size_t)n * 32;

    void *pP, *pO, *pDeg, *pCnt;
    void *pAfcH, *pAfcL, *pH2H, *pH2L, *pHDH, *pHDL, *pAzH, *pAzL, *pWH, *pWL;
    cudaGetSymbolAddress(&pP,    g_P);
    cudaGetSymbolAddress(&pO,    g_O);
    cudaGetSymbolAddress(&pDeg,  g_deg);
    cudaGetSymbolAddress(&pCnt,  g_cnt);
    cudaGetSymbolAddress(&pAfcH, g_AfcH);
    cudaGetSymbolAddress(&pAfcL, g_AfcL);
    cudaGetSymbolAddress(&pH2H,  g_H2H);
    cudaGetSymbolAddress(&pH2L,  g_H2L);
    cudaGetSymbolAddress(&pHDH,  g_HDH);
    cudaGetSymbolAddress(&pHDL,  g_HDL);
    cudaGetSymbolAddress(&pAzH,  g_AzH);
    cudaGetSymbolAddress(&pAzL,  g_AzL);
    cudaGetSymbolAddress(&pWH,   g_WH32);
    cudaGetSymbolAddress(&pWL,   g_WL32);
    float* P = (float*)pP;
    float* O = (float*)pO;
    __nv_bfloat16* AfcH = (__nv_bfloat16*)pAfcH;
    __nv_bfloat16* AfcL = (__nv_bfloat16*)pAfcL;
    __nv_bfloat16* H2H  = (__nv_bfloat16*)pH2H;
    __nv_bfloat16* H2L  = (__nv_bfloat16*)pH2L;
    __nv_bfloat16* HDH  = (__nv_bfloat16*)pHDH;
    __nv_bfloat16* HDL  = (__nv_bfloat16*)pHDL;
    __nv_bfloat16* AzH  = (__nv_bfloat16*)pAzH;
    __nv_bfloat16* AzL  = (__nv_bfloat16*)pAzL;
    uint32_t* WH = (uint32_t*)pWH;
    uint32_t* WL = (uint32_t*)pWL;

    const int SM128 = (4 * 128 * 20 + 4 * 16 * (128 + 8)) * 4;   // 75776
    const int SM64  = (4 * 128 * 20 + 4 * 16 * (64  + 8)) * 4;   // 59392
    cudaFuncSetAttribute(k_gemm_cp<128, 128, true,  true,  true >, cudaFuncAttributeMaxDynamicSharedMemorySize, SM128);
    cudaFuncSetAttribute(k_gemm_cp<64,  128, true,  true,  true >, cudaFuncAttributeMaxDynamicSharedMemorySize, SM128);
    cudaFuncSetAttribute(k_gemm_cp<256, 64,  false, false, false>, cudaFuncAttributeMaxDynamicSharedMemorySize, SM64);
    cudaFuncSetAttribute(k_gemm_cp<32,  128, true,  true,  true >, cudaFuncAttributeMaxDynamicSharedMemorySize, SM128);
    cudaFuncSetAttribute(k_gemm_cp<256, 128, false, false, false>, cudaFuncAttributeMaxDynamicSharedMemorySize, SM128);

    int gg = cdiv(n, 128);

    // ---- fused CSR build (kernel 1) ----
    cudaMemsetAsync(pDeg, 0, (size_t)n * sizeof(int));
    cudaMemsetAsync(pCnt, 0, sizeof(unsigned));
    k_csr<<<NB, 256>>>(eidx, e, n);

    // Pass A -> Afc planes (kernel 2)
    k_aggc<32, 16, false, 1><<<cdiv(n * 48, 256), 256>>>(
        (const float4*)feature, (const float4*)condition, nullptr,
        nullptr, AfcH, AfcL, n);

    // weight pre-pack (kernel 3)
    k_packw<<<cdiv(W_TOTAL32, 256), 256>>>(W_f2h, W_c2h_e, W_c2h_d,
                                           W_mean, W_logvar, W_z2h, W_out,
                                           b_mean, b_logvar);

    // Encoder projections (kernel 4 = f2h GEMM <- profiled)
    k_gemm_cp<128, 128, true, true, true><<<gg, 256, SM128>>>(
        (const uint32_t*)AfcH, (const uint32_t*)AfcL, 96,
        WH + OFF_F2H, WL + OFF_F2H, b_f2h,
        nullptr, H2H, H2L, 256, n,
        nullptr, nullptr, nullptr, nullptr, nullptr);

    // c2h encoder + decoder halves merged into one dual launch
    {
        dim3 grid(gg, 2);
        k_gemm_cp<64, 128, true, true, true><<<grid, 256, SM128>>>(
            (const uint32_t*)AfcH + 64, (const uint32_t*)AfcL + 64, 96,
            WH + OFF_C2HE, WL + OFF_C2HE, b_c2h_e,
            nullptr, H2H + 128, H2L + 128, 256, n,
            WH + OFF_C2HD, WL + OFF_C2HD, b_c2h_d,
            HDH + 128, HDL + 128);
    }

    // mean+logvar fused projection -> fp32 P
    k_gemm_cp<256, 64, false, false, false><<<gg, 256, SM64>>>(
        (const uint32_t*)H2H, (const uint32_t*)H2L, 128,
        WH + OFF_ML, WL + OFF_ML, nullptr,
        P, nullptr, nullptr, 64, n,
        nullptr, nullptr, nullptr, nullptr, nullptr);

    // Pass B fused with reparameterization
    k_aggB<<<cdiv(n * 8, 256), 256>>>((const float4*)P, (const float4*)noise,
                                      (float4*)oz, (float4*)om, (float4*)olv, n);

    // Pass C: Az = Agg(z) -> planes
    k_aggc<8, 0, false, 1><<<cdiv(n * 8, 256), 256>>>(
        (const float4*)oz, nullptr, nullptr, nullptr, AzH, AzL, n);

    // Decoder
    k_gemm_cp<32, 128, true, true, true><<<gg, 256, SM128>>>(
        (const uint32_t*)AzH, (const uint32_t*)AzL, 16,
        WH + OFF_Z2H, WL + OFF_Z2H, b_z2h,
        nullptr, HDH, HDL, 256, n,
        nullptr, nullptr, nullptr, nullptr, nullptr);
    k_gemm_cp<256, 128, false, false, false><<<gg, 256, SM128>>>(
        (const uint32_t*)HDH, (const uint32_t*)HDL, 128,
        WH + OFF_OUT, WL + OFF_OUT, nullptr,
        O, nullptr, nullptr, 128, n,
        nullptr, nullptr, nullptr, nullptr, nullptr);

    // Pass D: out = Agg(O) + b_out (fp32)
    k_aggc<32, 0, true, 0><<<cdiv(n * 32, 256), 256>>>(
        (const float4*)O, nullptr, (const float4*)b_out, (float4*)oo,
        nullptr, nullptr, n);
}

// round 17
// speedup vs baseline: 1.0736x; 1.0209x over previous
#include <cuda_runtime.h>
#include <cuda_bf16.h>
#include <math.h>
#include <stdint.h>

#define NN 50000
#define EE 800000
#define NB 296          // resident blocks for fused CSR kernel (148 SMs x 2)

// packed-weight offsets in uint32 (bf162-pair) units, layout [K/2][NC]
#define OFF_F2H   0
#define OFF_C2HE  8192
#define OFF_C2HD  12288
#define OFF_ML    16384
#define OFF_Z2H   24576
#define OFF_OUT   26624
#define W_TOTAL32 43008

// ---------------- scratch (static __device__, no runtime allocation) ----------------
__device__ float g_dis[NN];
__device__ int   g_deg[NN];
__device__ int   g_off[NN + 1];
__device__ int   g_cur[NN];
__device__ int   g_rows[EE];
__device__ int   g_cols[EE];
__device__ int2  g_sedge[EE];    // interleaved {src_row, weight_bits}
__device__ float g_P  [NN * 64];
__device__ float g_O  [NN * 128];
__device__ float g_bml[64];
__device__ __nv_bfloat16 g_AfcH[NN * 192], g_AfcL[NN * 192];
__device__ __nv_bfloat16 g_H2H [NN * 256], g_H2L [NN * 256];
__device__ __nv_bfloat16 g_HDH [NN * 256], g_HDL [NN * 256];
__device__ __nv_bfloat16 g_AzH [NN * 32],  g_AzL [NN * 32];
__device__ uint32_t g_WH32[W_TOTAL32], g_WL32[W_TOTAL32];
__device__ unsigned g_cnt;
__device__ int   g_part[512];

// ---------------- helpers ----------------
__device__ __forceinline__ uint32_t smem_u32(const void* p) {
    uint32_t a;
    asm("{ .reg .u64 t; cvta.to.shared.u64 t, %1; cvt.u32.u64 %0, t; }" : "=r"(a) : "l"(p));
    return a;
}
__device__ __forceinline__ void cp16(uint32_t dst, const void* src, uint32_t sz) {
    asm volatile("cp.async.ca.shared.global [%0], [%1], 16, %2;"
                 :: "r"(dst), "l"(__cvta_generic_to_global(src)), "r"(sz) : "memory");
}
#define CP_COMMIT() asm volatile("cp.async.commit_group;" ::: "memory")
#define CP_WAIT(N)  asm volatile("cp.async.wait_group %0;" :: "n"(N) : "memory")

// software grid barrier (all blocks co-resident)
__device__ __forceinline__ void gbar(unsigned step) {
    __syncthreads();
    if (threadIdx.x == 0) {
        __threadfence();
        atomicAdd(&g_cnt, 1u);
        unsigned target = step * gridDim.x;
        while (*(volatile unsigned*)&g_cnt < target) { }
        __threadfence();
    }
    __syncthreads();
}

// ---------------- fused CSR build ----------------
__global__ __launch_bounds__(256) void k_csr(const void* p, int e, int n) {
    int tid = threadIdx.x, bid = blockIdx.x;
    int gsz = gridDim.x * 256;
    int gi  = bid * 256 + tid;
    __shared__ int sh[256];

    const long long* q64 = (const long long*)p;
    long long probe = 0;
    if (gi < e) probe = q64[gi];
    int okl = (probe >= 0 && probe < (long long)n) ? 1 : 0;
    int is64 = __syncthreads_and(okl);

    for (int i = gi; i < e; i += gsz) {
        int r, c;
        if (is64) { r = (int)q64[i]; c = (int)q64[e + i]; }
        else { const int* q32 = (const int*)p; r = q32[i]; c = q32[e + i]; }
        g_rows[i] = r;
        g_cols[i] = c;
        atomicAdd(&g_deg[c], 1);
    }
    gbar(1);

    int chunk = (n + gridDim.x - 1) / gridDim.x;
    int s  = bid * chunk;
    int en = s + chunk; if (en > n) en = n;
    {
        int sum = 0;
        for (int i = s + tid; i < en; i += 256) sum += g_deg[i];
        sh[tid] = sum;
        __syncthreads();
        for (int o = 128; o > 0; o >>= 1) {
            if (tid < o) sh[tid] += sh[tid + o];
            __syncthreads();
        }
        if (tid == 0) g_part[bid] = sh[0];
    }
    gbar(2);

    int base;
    {
        int b = 0;
        for (int i = tid; i < bid; i += 256) b += g_part[i];
        __syncthreads();
        sh[tid] = b;
        __syncthreads();
        for (int o = 128; o > 0; o >>= 1) {
            if (tid < o) sh[tid] += sh[tid + o];
            __syncthreads();
        }
        base = sh[0];
        __syncthreads();
    }

    {
        int i = s + tid;
        int live = (tid < en - s);
        int d = live ? g_deg[i] : 0;
        sh[tid] = d;
        __syncthreads();
        for (int o = 1; o < 256; o <<= 1) {
            int v = (tid >= o) ? sh[tid - o] : 0;
            __syncthreads();
            sh[tid] += v;
            __syncthreads();
        }
        int excl = base + sh[tid] - d;
        if (live) {
            g_off[i] = excl;
            g_cur[i] = excl;
            g_dis[i] = rsqrtf((float)d + 1.0f);
        }
        if (bid == gridDim.x - 1 && tid == 0) g_off[n] = e;
    }
    gbar(3);

    for (int i = gi; i < e; i += gsz) {
        int r = g_rows[i], c = g_cols[i];
        int pos = atomicAdd(&g_cur[c], 1);
        int2 ed;
        ed.x = r;
        ed.y = __float_as_int(g_dis[r] * g_dis[c]);
        g_sedge[pos] = ed;
    }
}

// ---------------- weight pre-pack: fp32 -> bf162-pair hi/lo planes, [K/2][NC] ----------------
__global__ void k_packw(const float* __restrict__ Wf2h, const float* __restrict__ Wc2he,
                        const float* __restrict__ Wc2hd, const float* __restrict__ Wm,
                        const float* __restrict__ Wlv, const float* __restrict__ Wz2h,
                        const float* __restrict__ Wout,
                        const float* __restrict__ bm, const float* __restrict__ bl) {
    int idx = blockIdx.x * 256 + threadIdx.x;
    if (idx < 64) g_bml[idx] = (idx < 32) ? bm[idx] : bl[idx - 32];
    if (idx >= W_TOTAL32) return;
    float v0, v1;
    if (idx < OFF_C2HE) {
        int j = idx, kp = j / 128, n = j % 128;
        v0 = Wf2h[(2 * kp) * 128 + n]; v1 = Wf2h[(2 * kp + 1) * 128 + n];
    } else if (idx < OFF_C2HD) {
        int j = idx - OFF_C2HE, kp = j / 128, n = j % 128;
        v0 = Wc2he[(2 * kp) * 128 + n]; v1 = Wc2he[(2 * kp + 1) * 128 + n];
    } else if (idx < OFF_ML) {
        int j = idx - OFF_C2HD, kp = j / 128, n = j % 128;
        v0 = Wc2hd[(2 * kp) * 128 + n]; v1 = Wc2hd[(2 * kp + 1) * 128 + n];
    } else if (idx < OFF_Z2H) {
        int j = idx - OFF_ML, kp = j / 64, n = j % 64;
        if (n < 32) { v0 = Wm[(2 * kp) * 32 + n];  v1 = Wm[(2 * kp + 1) * 32 + n]; }
        else        { v0 = Wlv[(2 * kp) * 32 + n - 32]; v1 = Wlv[(2 * kp + 1) * 32 + n - 32]; }
    } else if (idx < OFF_OUT) {
        int j = idx - OFF_Z2H, kp = j / 128, n = j % 128;
        v0 = Wz2h[(2 * kp) * 128 + n]; v1 = Wz2h[(2 * kp + 1) * 128 + n];
    } else {
        int j = idx - OFF_OUT, kp = j / 128, n = j % 128;
        v0 = Wout[(2 * kp) * 128 + n]; v1 = Wout[(2 * kp + 1) * 128 + n];
    }
    __nv_bfloat16 h0 = __float2bfloat16_rn(v0);
    __nv_bfloat16 h1 = __float2bfloat16_rn(v1);
    __nv_bfloat16 l0 = __float2bfloat16_rn(v0 - __bfloat162float(h0));
    __nv_bfloat16 l1 = __float2bfloat16_rn(v1 - __bfloat162float(h1));
    uint16_t u0, u1, w0, w1;
    memcpy(&u0, &h0, 2); memcpy(&u1, &h1, 2);
    memcpy(&w0, &l0, 2); memcpy(&w1, &l1, 2);
    g_WH32[idx] = (uint32_t)u0 | ((uint32_t)u1 << 16);
    g_WL32[idx] = (uint32_t)w0 | ((uint32_t)w1 << 16);
}

// ---------------- CSR aggregation (OM: 0 fp32 out, 1 bf16 hi/lo split out) ----------------
template<int C0, int C1, bool BIAS, int OM>
__global__ __launch_bounds__(256) void k_aggc(
    const float4* __restrict__ s0, const float4* __restrict__ s1,
    const float4* __restrict__ bias, float4* __restrict__ dst,
    __nv_bfloat16* __restrict__ dsth, __nv_bfloat16* __restrict__ dstl, int n)
{
    constexpr int CT = C0 + C1;
    int idx = blockIdx.x * 256 + threadIdx.x;
    if (idx >= n * CT) return;
    int i = idx / CT, c = idx % CT;

    const float4* __restrict__ base;
    int stride;
    if (C1 == 0 || c < C0) { base = s0 + c;        stride = C0; }
    else                   { base = s1 + (c - C0); stride = C1; }

    float d = g_dis[i];
    float w0 = d * d;
    float4 v = base[(size_t)i * stride];
    float4 acc;
    acc.x = v.x * w0; acc.y = v.y * w0; acc.z = v.z * w0; acc.w = v.w * w0;

    int b = g_off[i], bend = g_off[i + 1];
    #pragma unroll 4
    for (int eix = b; eix < bend; eix++) {
        int2  ed = g_sedge[eix];
        float w  = __int_as_float(ed.y);
        float4 u = base[(size_t)ed.x * stride];
        acc.x += u.x * w; acc.y += u.y * w; acc.z += u.z * w; acc.w += u.w * w;
    }
    if (BIAS) {
        float4 bb = bias[c];
        acc.x += bb.x; acc.y += bb.y; acc.z += bb.z; acc.w += bb.w;
    }
    if (OM == 0) {
        dst[(size_t)i * CT + c] = acc;
    } else {
        __nv_bfloat162 h01, h23, l01, l23;
        h01.x = __float2bfloat16_rn(acc.x);
        h01.y = __float2bfloat16_rn(acc.y);
        h23.x = __float2bfloat16_rn(acc.z);
        h23.y = __float2bfloat16_rn(acc.w);
        l01.x = __float2bfloat16_rn(acc.x - __bfloat162float(h01.x));
        l01.y = __float2bfloat16_rn(acc.y - __bfloat162float(h01.y));
        l23.x = __float2bfloat16_rn(acc.z - __bfloat162float(h23.x));
        l23.y = __float2bfloat16_rn(acc.w - __bfloat162float(h23.y));
        size_t o = ((size_t)i * CT + c) * 4;
        uint2 hp, lp;
        hp.x = *(uint32_t*)&h01; hp.y = *(uint32_t*)&h23;
        lp.x = *(uint32_t*)&l01; lp.y = *(uint32_t*)&l23;
        *(uint2*)&dsth[o] = hp;
        *(uint2*)&dstl[o] = lp;
    }
}

// ---------------- fused pass B: Agg(P)+bias, then reparameterize ----------------
__global__ __launch_bounds__(256) void k_aggB(
    const float4* __restrict__ P, const float4* __restrict__ noise,
    float4* __restrict__ oz, float4* __restrict__ om, float4* __restrict__ olv, int n)
{
    int idx = blockIdx.x * 256 + threadIdx.x;
    if (idx >= n * 8) return;
    int i = idx / 8, c = idx % 8;

    float d = g_dis[i];
    float w0 = d * d;
    float4 vm = P[(size_t)i * 16 + c];
    float4 vl = P[(size_t)i * 16 + c + 8];
    float4 am, al;
    am.x = vm.x * w0; am.y = vm.y * w0; am.z = vm.z * w0; am.w = vm.w * w0;
    al.x = vl.x * w0; al.y = vl.y * w0; al.z = vl.z * w0; al.w = vl.w * w0;

    int b = g_off[i], bend = g_off[i + 1];
    #pragma unroll 4
    for (int eix = b; eix < bend; eix++) {
        int2  ed = g_sedge[eix];
        float w  = __int_as_float(ed.y);
        float4 um = P[(size_t)ed.x * 16 + c];
        float4 ul = P[(size_t)ed.x * 16 + c + 8];
        am.x += um.x * w; am.y += um.y * w; am.z += um.z * w; am.w += um.w * w;
        al.x += ul.x * w; al.y += ul.y * w; al.z += ul.z * w; al.w += ul.w * w;
    }
    const float4* bml4 = (const float4*)g_bml;
    float4 bm = bml4[c], blv = bml4[c + 8];
    am.x += bm.x;  am.y += bm.y;  am.z += bm.z;  am.w += bm.w;
    al.x += blv.x; al.y += blv.y; al.z += blv.z; al.w += blv.w;

    float4 nv = noise[idx];
    float4 zv;
    zv.x = nv.x * expf(0.5f * al.x) + am.x;
    zv.y = nv.y * expf(0.5f * al.y) + am.y;
    zv.z = nv.z * expf(0.5f * al.z) + am.z;
    zv.w = nv.w * expf(0.5f * al.w) + am.w;

    oz[idx]  = zv;
    om[idx]  = am;
    olv[idx] = al;
}

// ---------------- cp.async double-buffered split-bf16 tensor-core GEMM ----------------
// Optional dual-mode: gridDim.y==2 selects second weight/bias/output set (same A).
__device__ __forceinline__ void mma_bf16(float* d,
    uint32_t a0, uint32_t a1, uint32_t a2, uint32_t a3,
    uint32_t b0, uint32_t b1)
{
    asm volatile(
        "mma.sync.aligned.m16n8k16.row.col.f32.bf16.bf16.f32 "
        "{%0,%1,%2,%3}, {%4,%5,%6,%7}, {%8,%9}, {%0,%1,%2,%3};\n"
        : "+f"(d[0]), "+f"(d[1]), "+f"(d[2]), "+f"(d[3])
        : "r"(a0), "r"(a1), "r"(a2), "r"(a3), "r"(b0), "r"(b1));
}

template<int K, int NC, bool BIAS, bool TANH, bool SPLITOUT>
__global__ __launch_bounds__(256, 2) void k_gemm_cp(
    const uint32_t* __restrict__ Ah, const uint32_t* __restrict__ Al, int ldau,
    const uint32_t* __restrict__ Wh, const uint32_t* __restrict__ Wl,
    const float* __restrict__ bias,
    float* __restrict__ C, __nv_bfloat16* __restrict__ Ch, __nv_bfloat16* __restrict__ Cl,
    int ldc, int M,
    const uint32_t* Wh2, const uint32_t* Wl2, const float* bias2,
    __nv_bfloat16* Ch2, __nv_bfloat16* Cl2)
{
    constexpr int BM = 128;
    constexpr int PA = 20;
    constexpr int PW = NC + 8;
    constexpr int WN = NC / 4;
    constexpr int NJ = WN / 8;
    constexpr int NK = K / 32;
    constexpr int ASZ = BM * PA;
    constexpr int WSZ = 16 * PW;

    if (blockIdx.y == 1) {
        Wh = Wh2; Wl = Wl2; bias = bias2; Ch = Ch2; Cl = Cl2;
    }

    extern __shared__ uint32_t smem32[];
    uint32_t sb = smem_u32(smem32);

    int tid  = threadIdx.x;
    int lane = tid & 31;
    int wid  = tid >> 5;
    int warpM = wid >> 2, warpN = wid & 3;
    int wr0 = warpM * 64;
    int wc0 = warpN * WN;
    int g = lane >> 2, q = lane & 3;
    int m0 = blockIdx.x * BM;

    float acc[4][NJ][4];
    #pragma unroll
    for (int mi = 0; mi < 4; mi++)
        #pragma unroll
        for (int nj = 0; nj < NJ; nj++)
            #pragma unroll
            for (int t = 0; t < 4; t++) acc[mi][nj][t] = 0.0f;

    auto fill = [&](int ck, int b) {
        int kpb = ck * 16;
        uint32_t aH = sb + (uint32_t)((b * 2 + 0) * ASZ) * 4;
        uint32_t aL = sb + (uint32_t)((b * 2 + 1) * ASZ) * 4;
        uint32_t wH = sb + (uint32_t)(4 * ASZ + (b * 2 + 0) * WSZ) * 4;
        uint32_t wL = sb + (uint32_t)(4 * ASZ + (b * 2 + 1) * WSZ) * 4;
        #pragma unroll
        for (int f = tid; f < BM * 4; f += 256) {
            int r = f >> 2, seg = f & 3;
            int gr = m0 + r;
            uint32_t sz = (gr < M) ? 16u : 0u;
            size_t go = (size_t)gr * ldau + kpb + seg * 4;
            uint32_t so = (uint32_t)(r * PA + seg * 4) * 4;
            cp16(aH + so, Ah + go, sz);
            cp16(aL + so, Al + go, sz);
        }
        #pragma unroll
        for (int f = tid; f < 4 * NC; f += 256) {
            int kp2 = f / (NC / 4);
            int seg = f % (NC / 4);
            size_t go = (size_t)(kpb + kp2) * NC + seg * 4;
            uint32_t so = (uint32_t)(kp2 * PW + seg * 4) * 4;
            cp16(wH + so, Wh + go, 16u);
            cp16(wL + so, Wl + go, 16u);
        }
    };

    fill(0, 0);
    CP_COMMIT();

    for (int ck = 0; ck < NK; ck++) {
        if (ck + 1 < NK) fill(ck + 1, (ck + 1) & 1);
        CP_COMMIT();
        if (ck + 1 < NK) { CP_WAIT(1); } else { CP_WAIT(0); }
        __syncthreads();

        int b = ck & 1;
        const uint32_t* sAh = smem32 + (b * 2 + 0) * ASZ;
        const uint32_t* sAl = smem32 + (b * 2 + 1) * ASZ;
        const uint32_t* sWh = smem32 + 4 * ASZ + (b * 2 + 0) * WSZ;
        const uint32_t* sWl = smem32 + 4 * ASZ + (b * 2 + 1) * WSZ;

        #pragma unroll
        for (int s = 0; s < 2; s++) {
            uint32_t bh[NJ][2], bl[NJ][2];
            int kp0 = s * 8 + q;
            #pragma unroll
            for (int nj = 0; nj < NJ; nj++) {
                int nn = wc0 + nj * 8 + g;
                bh[nj][0] = sWh[kp0 * PW + nn];
                bh[nj][1] = sWh[(kp0 + 4) * PW + nn];
                bl[nj][0] = sWl[kp0 * PW + nn];
                bl[nj][1] = sWl[(kp0 + 4) * PW + nn];
            }
            #pragma unroll
            for (int mi = 0; mi < 4; mi++) {
                int r = wr0 + mi * 16 + g;
                uint32_t ah0 = sAh[r * PA + kp0];
                uint32_t ah1 = sAh[(r + 8) * PA + kp0];
                uint32_t ah2 = sAh[r * PA + kp0 + 4];
                uint32_t ah3 = sAh[(r + 8) * PA + kp0 + 4];
                uint32_t al0 = sAl[r * PA + kp0];
                uint32_t al1 = sAl[(r + 8) * PA + kp0];
                uint32_t al2 = sAl[r * PA + kp0 + 4];
                uint32_t al3 = sAl[(r + 8) * PA + kp0 + 4];
                #pragma unroll
                for (int nj = 0; nj < NJ; nj++) {
                    mma_bf16(acc[mi][nj], ah0, ah1, ah2, ah3, bh[nj][0], bh[nj][1]);
                    mma_bf16(acc[mi][nj], ah0, ah1, ah2, ah3, bl[nj][0], bl[nj][1]);
                    mma_bf16(acc[mi][nj], al0, al1, al2, al3, bh[nj][0], bh[nj][1]);
                }
            }
        }
        __syncthreads();
    }

    // ---- epilogue ----
    #pragma unroll
    for (int mi = 0; mi < 4; mi++) {
        #pragma unroll
        for (int nj = 0; nj < NJ; nj++) {
            int c  = wc0 + nj * 8 + 2 * q;
            float b0v = 0.f, b1v = 0.f;
            if (BIAS) { b0v = bias[c]; b1v = bias[c + 1]; }
            int r0 = m0 + wr0 + mi * 16 + g;
            float v0 = acc[mi][nj][0] + b0v;
            float v1 = acc[mi][nj][1] + b1v;
            float v2 = acc[mi][nj][2] + b0v;
            float v3 = acc[mi][nj][3] + b1v;
            if (TANH) { v0 = tanhf(v0); v1 = tanhf(v1); v2 = tanhf(v2); v3 = tanhf(v3); }
            if (SPLITOUT) {
                if (r0 < M) {
                    __nv_bfloat162 hh, ll;
                    hh.x = __float2bfloat16_rn(v0); hh.y = __float2bfloat16_rn(v1);
                    ll.x = __float2bfloat16_rn(v0 - __bfloat162float(hh.x));
                    ll.y = __float2bfloat16_rn(v1 - __bfloat162float(hh.y));
                    *(uint32_t*)&Ch[(size_t)r0 * ldc + c] = *(uint32_t*)&hh;
                    *(uint32_t*)&Cl[(size_t)r0 * ldc + c] = *(uint32_t*)&ll;
                }
                if (r0 + 8 < M) {
                    __nv_bfloat162 hh, ll;
                    hh.x = __float2bfloat16_rn(v2); hh.y = __float2bfloat16_rn(v3);
                    ll.x = __float2bfloat16_rn(v2 - __bfloat162float(hh.x));
                    ll.y = __float2bfloat16_rn(v3 - __bfloat162float(hh.y));
                    *(uint32_t*)&Ch[(size_t)(r0 + 8) * ldc + c] = *(uint32_t*)&hh;
                    *(uint32_t*)&Cl[(size_t)(r0 + 8) * ldc + c] = *(uint32_t*)&ll;
                }
            } else {
                if (r0 < M) {
                    float2 o; o.x = v0; o.y = v1;
                    *(float2*)&C[(size_t)r0 * ldc + c] = o;
                }
                if (r0 + 8 < M) {
                    float2 o; o.x = v2; o.y = v3;
                    *(float2*)&C[(size_t)(r0 + 8) * ldc + c] = o;
                }
            }
        }
    }
}

// ---------------- launch ----------------
static inline int cdiv(int a, int b) { return (a + b - 1) / b; }

extern "C" void kernel_launch(void* const* d_in, const int* in_sizes, int n_in,
                              void* d_out, int out_size) {
    const float* feature   = (const float*)d_in[0];
    const float* condition = (const float*)d_in[1];
    const float* noise     = (const float*)d_in[2];
    const float* W_f2h     = (const float*)d_in[3];
    const float* b_f2h     = (const float*)d_in[4];
    const float* W_c2h_e   = (const float*)d_in[5];
    const float* b_c2h_e   = (const float*)d_in[6];
    const float* W_mean    = (const float*)d_in[7];
    const float* b_mean    = (const float*)d_in[8];
    const float* W_logvar  = (const float*)d_in[9];
    const float* b_logvar  = (const float*)d_in[10];
    const float* W_z2h     = (const float*)d_in[11];
    const float* b_z2h     = (const float*)d_in[12];
    const float* W_c2h_d   = (const float*)d_in[13];
    const float* b_c2h_d   = (const float*)d_in[14];
    const float* W_out     = (const float*)d_in[15];
    const float* b_out     = (const float*)d_in[16];
    const void*  eidx      = d_in[17];

    int n = in_sizes[0] / 128;
    int e = in_sizes[17] / 2;

    float* oz  = (float*)d_out;
    float* om  = oz  + (size_t)n * 32;
    float* olv = om  + (size_t)n * 32;
    float* oo  = olv + (size_t)n * 32;

    void *pP, *pO, *pDeg, *pCnt;
    void *pAfcH, *pAfcL, *pH2H, *pH2L, *pHDH, *pHDL, *pAzH, *pAzL, *pWH, *pWL;
    cudaGetSymbolAddress(&pP,    g_P);
    cudaGetSymbolAddress(&pO,    g_O);
    cudaGetSymbolAddress(&pDeg,  g_deg);
    cudaGetSymbolAddress(&pCnt,  g_cnt);
    cudaGetSymbolAddress(&pAfcH, g_AfcH);
    cudaGetSymbolAddress(&pAfcL, g_AfcL);
    cudaGetSymbolAddress(&pH2H,  g_H2H);
    cudaGetSymbolAddress(&pH2L,  g_H2L);
    cudaGetSymbolAddress(&pHDH,  g_HDH);
    cudaGetSymbolAddress(&pHDL,  g_HDL);
    cudaGetSymbolAddress(&pAzH,  g_AzH);
    cudaGetSymbolAddress(&pAzL,  g_AzL);
    cudaGetSymbolAddress(&pWH,   g_WH32);
    cudaGetSymbolAddress(&pWL,   g_WL32);
    float* P = (float*)pP;
    float* O = (float*)pO;
    __nv_bfloat16* AfcH = (__nv_bfloat16*)pAfcH;
    __nv_bfloat16* AfcL = (__nv_bfloat16*)pAfcL;
    __nv_bfloat16* H2H  = (__nv_bfloat16*)pH2H;
    __nv_bfloat16* H2L  = (__nv_bfloat16*)pH2L;
    __nv_bfloat16* HDH  = (__nv_bfloat16*)pHDH;
    __nv_bfloat16* HDL  = (__nv_bfloat16*)pHDL;
    __nv_bfloat16* AzH  = (__nv_bfloat16*)pAzH;
    __nv_bfloat16* AzL  = (__nv_bfloat16*)pAzL;
    uint32_t* WH = (uint32_t*)pWH;
    uint32_t* WL = (uint32_t*)pWL;

    const int SM128 = (4 * 128 * 20 + 4 * 16 * (128 + 8)) * 4;   // 75776
    const int SM64  = (4 * 128 * 20 + 4 * 16 * (64  + 8)) * 4;   // 59392
    cudaFuncSetAttribute(k_gemm_cp<128, 128, true,  true,  true >, cudaFuncAttributeMaxDynamicSharedMemorySize, SM128);
    cudaFuncSetAttribute(k_gemm_cp<64,  128, true,  true,  true >, cudaFuncAttributeMaxDynamicSharedMemorySize, SM128);
    cudaFuncSetAttribute(k_gemm_cp<256, 64,  false, false, false>, cudaFuncAttributeMaxDynamicSharedMemorySize, SM64);
    cudaFuncSetAttribute(k_gemm_cp<32,  128, true,  true,  true >, cudaFuncAttributeMaxDynamicSharedMemorySize, SM128);
    cudaFuncSetAttribute(k_gemm_cp<256, 128, false, false, false>, cudaFuncAttributeMaxDynamicSharedMemorySize, SM128);

    int gg = cdiv(n, 128);

    // ---- fused CSR build (kernel 1) ----
    cudaMemsetAsync(pDeg, 0, (size_t)n * sizeof(int));
    cudaMemsetAsync(pCnt, 0, sizeof(unsigned));
    k_csr<<<NB, 256>>>(eidx, e, n);

    // Pass A -> Afc planes (kernel 2)
    k_aggc<32, 16, false, 1><<<cdiv(n * 48, 256), 256>>>(
        (const float4*)feature, (const float4*)condition, nullptr,
        nullptr, AfcH, AfcL, n);

    // weight pre-pack (kernel 3)
    k_packw<<<cdiv(W_TOTAL32, 256), 256>>>(W_f2h, W_c2h_e, W_c2h_d,
                                           W_mean, W_logvar, W_z2h, W_out,
                                           b_mean, b_logvar);

    // Encoder projections (kernel 4 = f2h GEMM <- profiled)
    k_gemm_cp<128, 128, true, true, true><<<gg, 256, SM128>>>(
        (const uint32_t*)AfcH, (const uint32_t*)AfcL, 96,
        WH + OFF_F2H, WL + OFF_F2H, b_f2h,
        nullptr, H2H, H2L, 256, n,
        nullptr, nullptr, nullptr, nullptr, nullptr);

    // c2h encoder + decoder halves merged into one dual launch
    {
        dim3 grid(gg, 2);
        k_gemm_cp<64, 128, true, true, true><<<grid, 256, SM128>>>(
            (const uint32_t*)AfcH + 64, (const uint32_t*)AfcL + 64, 96,
            WH + OFF_C2HE, WL + OFF_C2HE, b_c2h_e,
            nullptr, H2H + 128, H2L + 128, 256, n,
            WH + OFF_C2HD, WL + OFF_C2HD, b_c2h_d,
            HDH + 128, HDL + 128);
    }

    // mean+logvar fused projection -> fp32 P
    k_gemm_cp<256, 64, false, false, false><<<gg, 256, SM64>>>(
        (const uint32_t*)H2H, (const uint32_t*)H2L, 128,
        WH + OFF_ML, WL + OFF_ML, nullptr,
        P, nullptr, nullptr, 64, n,
        nullptr, nullptr, nullptr, nullptr, nullptr);

    // Pass B fused with reparameterization
    k_aggB<<<cdiv(n * 8, 256), 256>>>((const float4*)P, (const float4*)noise,
                                      (float4*)oz, (float4*)om, (float4*)olv, n);

    // Pass C: Az = Agg(z) -> planes
    k_aggc<8, 0, false, 1><<<cdiv(n * 8, 256), 256>>>(
        (const float4*)oz, nullptr, nullptr, nullptr, AzH, AzL, n);

    // Decoder
    k_gemm_cp<32, 128, true, true, true><<<gg, 256, SM128>>>(
        (const uint32_t*)AzH, (const uint32_t*)AzL, 16,
        WH + OFF_Z2H, WL + OFF_Z2H, b_z2h,
        nullptr, HDH, HDL, 256, n,
        nullptr, nullptr, nullptr, nullptr, nullptr);
    k_gemm_cp<256, 128, false, false, false><<<gg, 256, SM128>>>(
        (const uint32_t*)HDH, (const uint32_t*)HDL, 128,
        WH + OFF_OUT, WL + OFF_OUT, nullptr,
        O, nullptr, nullptr, 128, n,
        nullptr, nullptr, nullptr, nullptr, nullptr);

    // Pass D: out = Agg(O) + b_out (fp32)
    k_aggc<32, 0, true, 0><<<cdiv(n * 32, 256), 256>>>(
        (const float4*)O, nullptr, (const float4*)b_out, (float4*)oo,
        nullptr, nullptr, n);
}